// round 13
// baseline (speedup 1.0000x reference)
#include <cuda_runtime.h>
#include <cuda_bf16.h>
#include <cstdint>

// Problem constants
#define BB   128
#define TT   1024
#define II   256
#define HH   512
#define CC   32

#define GR   8          // CTAs per group (W split 8 ways)
#define NG   16         // 16 groups (8 batches each)
#define BG   8          // batches per group
#define JS   64         // j rows per CTA

typedef unsigned long long ull;

// ---------------- generic asm helpers ----------------

__device__ __forceinline__ unsigned smem_u32(const void* p) {
    return (unsigned)__cvta_generic_to_shared(p);
}

__device__ __forceinline__ float lds32v(unsigned a) {
    float v;
    asm volatile("ld.shared.f32 %0, [%1];" : "=f"(v) : "r"(a));
    return v;
}

__device__ __forceinline__ void sts128v(unsigned a, uint4 v) {
    asm volatile("st.shared.v4.b32 [%0], {%1,%2,%3,%4};"
                 :: "r"(a), "r"(v.x), "r"(v.y), "r"(v.z), "r"(v.w) : "memory");
}

__device__ __forceinline__ void sts64u(unsigned a, uint32_t x, uint32_t y) {
    asm volatile("st.shared.v2.b32 [%0], {%1,%2};"
                 :: "r"(a), "r"(x), "r"(y) : "memory");
}

__device__ __forceinline__ void sts64f(unsigned a, float x, float y) {
    asm volatile("st.shared.v2.f32 [%0], {%1,%2};"
                 :: "r"(a), "f"(x), "f"(y) : "memory");
}

__device__ __forceinline__ void ldsm_x4(unsigned addr, uint32_t& r0, uint32_t& r1,
                                        uint32_t& r2, uint32_t& r3) {
    asm volatile("ldmatrix.sync.aligned.m8n8.x4.shared.b16 {%0,%1,%2,%3}, [%4];"
                 : "=r"(r0), "=r"(r1), "=r"(r2), "=r"(r3) : "r"(addr));
}

__device__ __forceinline__ void ldsm_x2(unsigned addr, uint32_t& r0, uint32_t& r1) {
    asm volatile("ldmatrix.sync.aligned.m8n8.x2.shared.b16 {%0,%1}, [%2];"
                 : "=r"(r0), "=r"(r1) : "r"(addr));
}

__device__ __forceinline__ void mma16816(float* c, const uint32_t* a,
                                         uint32_t b0, uint32_t b1) {
    asm volatile(
        "mma.sync.aligned.m16n8k16.row.col.f32.bf16.bf16.f32 "
        "{%0,%1,%2,%3}, {%4,%5,%6,%7}, {%8,%9}, {%0,%1,%2,%3};"
        : "+f"(c[0]), "+f"(c[1]), "+f"(c[2]), "+f"(c[3])
        : "r"(a[0]), "r"(a[1]), "r"(a[2]), "r"(a[3]), "r"(b0), "r"(b1));
}

__device__ __forceinline__ uint32_t prmt(uint32_t a, uint32_t b, uint32_t sel) {
    uint32_t d;
    asm("prmt.b32 %0, %1, %2, %3;" : "=r"(d) : "r"(a), "r"(b), "r"(sel));
    return d;
}

// split a float4 into bf16x2 hi/lo register pairs
__device__ __forceinline__ void split4(float4 v, uint2& hv, uint2& lv) {
    __nv_bfloat162 h01 = __floats2bfloat162_rn(v.x, v.y);
    __nv_bfloat162 h23 = __floats2bfloat162_rn(v.z, v.w);
    float l0 = v.x - __bfloat162float(h01.x);
    float l1 = v.y - __bfloat162float(h01.y);
    float l2 = v.z - __bfloat162float(h23.x);
    float l3 = v.w - __bfloat162float(h23.y);
    __nv_bfloat162 q01 = __floats2bfloat162_rn(l0, l1);
    __nv_bfloat162 q23 = __floats2bfloat162_rn(l2, l3);
    hv = make_uint2(*(uint32_t*)&h01, *(uint32_t*)&h23);
    lv = make_uint2(*(uint32_t*)&q01, *(uint32_t*)&q23);
}

// ---------------- Pre-pass: split x and W_ih into bf16 hi/lo ----------------

#define NX4 ((BB * TT * II) / 4)   // 8388608 float4 groups
#define NW4 ((HH * II) / 4)        // 32768

__device__ __nv_bfloat16 g_xhi[BB * TT * II];
__device__ __nv_bfloat16 g_xlo[BB * TT * II];
__device__ __nv_bfloat16 g_whi[HH * II];
__device__ __nv_bfloat16 g_wlo[HH * II];

__global__ void __launch_bounds__(256)
cvt_kernel(const float* __restrict__ x, const float* __restrict__ w)
{
    const int stride = gridDim.x * blockDim.x;
    for (int i = blockIdx.x * blockDim.x + threadIdx.x; i < NX4 + NW4; i += stride) {
        float4 v = (i < NX4) ? ((const float4*)x)[i]
                             : ((const float4*)w)[i - NX4];
        uint2 hv, lv;
        split4(v, hv, lv);
        if (i < NX4) {
            ((uint2*)g_xhi)[i] = hv;
            ((uint2*)g_xlo)[i] = lv;
        } else {
            ((uint2*)g_whi)[i - NX4] = hv;
            ((uint2*)g_wlo)[i - NX4] = lv;
        }
    }
}

// ---------------- Kernel A: xp via mma.sync bf16 split-precision (R10) ---------

#define KC     64
#define ASTR   72                     // bf16 stride
#define XA_HI  0
#define XA_LO  (128 * ASTR * 2)       // 18432
#define XB_HI  (2 * 128 * ASTR * 2)   // 36864
#define XB_LO  (XB_HI + 64 * ASTR * 2)
#define SMEM_X (XB_LO + 64 * ASTR * 2)  // 55296 bytes

__global__ void __launch_bounds__(256)
xp_mma_kernel(const float* __restrict__ bias, float* __restrict__ out)
{
    extern __shared__ char smx[];
    const unsigned sb = smem_u32(smx);
    const int tid = threadIdx.x;
    const int wid = tid >> 5;
    const int lane = tid & 31;
    const int h0 = blockIdx.x * 64;
    const int m0 = blockIdx.y * 128;

    const int wr = wid >> 1;
    const int wc = wid & 1;

    float acc[2][4][4];
#pragma unroll
    for (int mt = 0; mt < 2; mt++)
#pragma unroll
        for (int nt = 0; nt < 4; nt++)
#pragma unroll
            for (int i = 0; i < 4; i++) acc[mt][nt][i] = 0.0f;

    const int a_row = wr * 32 + (lane & 15);
    const int a_col = (lane >> 4) * 8;
    const unsigned a_addr0 = sb + XA_HI + (unsigned)((a_row * ASTR + a_col) * 2);
    const int b_n = wc * 32 + (lane & 7) + (lane >> 4) * 8;
    const int b_k = ((lane >> 3) & 1) * 8;
    const unsigned b_addr0 = sb + XB_HI + (unsigned)((b_n * ASTR + b_k) * 2);

    for (int ch = 0; ch < 4; ch++) {
        __syncthreads();
        {
#pragma unroll
            for (int i = 0; i < 4; i++) {
                int idx = tid + i * 256;
                int row = idx >> 3;
                int c8 = idx & 7;
                size_t src = (size_t)(m0 + row) * II + ch * KC + c8 * 8;
                unsigned dst = (unsigned)((row * ASTR + c8 * 8) * 2);
                sts128v(sb + XA_HI + dst, *(const uint4*)(g_xhi + src));
                sts128v(sb + XA_LO + dst, *(const uint4*)(g_xlo + src));
            }
        }
        {
#pragma unroll
            for (int i = 0; i < 2; i++) {
                int idx = tid + i * 256;
                int row = idx >> 3;
                int c8 = idx & 7;
                size_t src = (size_t)(h0 + row) * II + ch * KC + c8 * 8;
                unsigned dst = (unsigned)((row * ASTR + c8 * 8) * 2);
                sts128v(sb + XB_HI + dst, *(const uint4*)(g_whi + src));
                sts128v(sb + XB_LO + dst, *(const uint4*)(g_wlo + src));
            }
        }
        __syncthreads();

#pragma unroll
        for (int kk = 0; kk < 4; kk++) {
            const unsigned akk = (unsigned)(kk * 16 * 2);
            uint32_t ah[2][4], al[2][4];
#pragma unroll
            for (int mt = 0; mt < 2; mt++) {
                unsigned ao = a_addr0 + akk + (unsigned)(mt * 16 * ASTR * 2);
                ldsm_x4(ao, ah[mt][0], ah[mt][1], ah[mt][2], ah[mt][3]);
                ldsm_x4(ao + (XA_LO - XA_HI),
                        al[mt][0], al[mt][1], al[mt][2], al[mt][3]);
            }
            uint32_t bh[2][4], bl[2][4];
#pragma unroll
            for (int np = 0; np < 2; np++) {
                unsigned bo = b_addr0 + akk + (unsigned)(np * 16 * ASTR * 2);
                ldsm_x4(bo, bh[np][0], bh[np][1], bh[np][2], bh[np][3]);
                ldsm_x4(bo + (XB_LO - XB_HI),
                        bl[np][0], bl[np][1], bl[np][2], bl[np][3]);
            }
#pragma unroll
            for (int mt = 0; mt < 2; mt++)
#pragma unroll
                for (int np = 0; np < 2; np++)
#pragma unroll
                    for (int sub = 0; sub < 2; sub++) {
                        float* c = acc[mt][np * 2 + sub];
                        mma16816(c, ah[mt], bh[np][sub * 2], bh[np][sub * 2 + 1]);
                        mma16816(c, ah[mt], bl[np][sub * 2], bl[np][sub * 2 + 1]);
                        mma16816(c, al[mt], bh[np][sub * 2], bh[np][sub * 2 + 1]);
                    }
        }
    }

    const int g = lane >> 2;
    const int tig = lane & 3;
#pragma unroll
    for (int mt = 0; mt < 2; mt++) {
        const int row0 = m0 + wr * 32 + mt * 16 + g;
#pragma unroll
        for (int nt = 0; nt < 4; nt++) {
            const int col = h0 + wc * 32 + nt * 8 + tig * 2;
            float2 bv = *(const float2*)&bias[col];
            float* c = acc[mt][nt];
            float2 o0 = make_float2(c[0] + bv.x, c[1] + bv.y);
            float2 o1 = make_float2(c[2] + bv.x, c[3] + bv.y);
            *(float2*)&out[(size_t)row0 * HH + col] = o0;
            *(float2*)&out[(size_t)(row0 + 8) * HH + col] = o1;
        }
    }
}

// ---------------- Kernel B ------------------------------------------------------

__device__ float    g_cp[BB * HH];
__device__ unsigned g_hp[2][BB][HH];     // packed bf16 hi|lo h exchange
__device__ int      g_flag[NG][GR * 8];  // per-rank step flags (32B padded)

__global__ void __launch_bounds__(512)
cp_kernel(const float* __restrict__ cons, const float* __restrict__ W_ch,
          const float* __restrict__ b_ch, const float* __restrict__ b_hh)
{
    __shared__ float cs[CC];
    const int b = blockIdx.x;
    const int h = threadIdx.x;
    if (h < CC) cs[h] = cons[b * CC + h];
    __syncthreads();
    float s = b_ch[h] + b_hh[h];
#pragma unroll
    for (int c = 0; c < CC; c++) s += cs[c] * W_ch[h * CC + c];
    g_cp[b * HH + h] = s;
}

// ---------------- Kernel C: recurrence (R11 geometry + flags + packed exchange) -
// Per CTA (group g, rank r): D[64j,8b] = Wslice[64,512] @ h^T via bf16 split
// mma.sync. 8 warps = 4 m-tiles x 2 k-halves; owner sums 2 frag partials.
// Exchange: packed bf16 hi|lo words via L2; per-rank release-flags (value =
// step+1); each staging thread polls only its source rank.

#define WSTR    520                   // bf16 row stride (1040B == 16 mod 128)
#define WHI_OFF 0
#define WLO_OFF (JS * WSTR * 2)                 // 66560
#define HHI_OFF (2 * JS * WSTR * 2)             // 133120
#define HLO_OFF (HHI_OFF + BG * WSTR * 2)       // 141440
#define FRAG_OFF (HLO_OFF + BG * WSTR * 2)      // 149760
#define FRW     10                    // frag row stride (floats)
#define SMEM_C  (FRAG_OFF + 2 * JS * FRW * 4 + 128)  // ~155 KB

__global__ void __launch_bounds__(256, 1)
rnn_scan_kernel(float* __restrict__ out, const float* __restrict__ W_hh,
                const int* __restrict__ lengths)
{
    extern __shared__ char smc[];
    const unsigned sb = smem_u32(smc);
    const int tid = threadIdx.x;
    const int r = blockIdx.x & 7;
    const int g = blockIdx.x >> 3;

    // one-time: convert W slice to bf16 hi/lo in SMEM
    for (int idx = tid; idx < (JS * HH) / 4; idx += 256) {
        int j = idx >> 7;
        int k4 = (idx & 127) * 4;
        float4 v = *(const float4*)&W_hh[(size_t)(r * JS + j) * HH + k4];
        uint2 hv, lv;
        split4(v, hv, lv);
        unsigned dst = sb + WHI_OFF + (unsigned)((j * WSTR + k4) * 2);
        sts64u(dst, hv.x, hv.y);
        sts64u(dst + (WLO_OFF - WHI_OFF), lv.x, lv.y);
    }
    // zero h hi/lo (h at t=0 is 0)
    for (int idx = tid; idx < (2 * BG * WSTR * 2) / 4; idx += 256) {
        asm volatile("st.shared.b32 [%0], %1;"
                     :: "r"(sb + HHI_OFF + (unsigned)(idx * 4)), "r"(0u) : "memory");
    }

    const int wid = tid >> 5;
    const int lane = tid & 31;
    const int mt = wid >> 1;            // m-tile (0..3)
    const int kh = wid & 1;             // k-half (0..1)

    // ldsm addresses (validated maps)
    const unsigned aHi = sb + WHI_OFF +
        (unsigned)(((mt * 16 + (lane & 15)) * WSTR + kh * 256 + (lane >> 4) * 8) * 2);
    const unsigned aLo = aHi + (WLO_OFF - WHI_OFF);
    const int l4 = lane & 15;
    const unsigned bHi = sb + HHI_OFF +
        (unsigned)(((l4 & 7) * WSTR + kh * 256 + ((l4 >> 3) & 1) * 8) * 2);
    const unsigned bLo = bHi + (HLO_OFF - HHI_OFF);

    // frag store addrs
    const unsigned fr0 = sb + FRAG_OFF +
        (unsigned)(((kh * JS + mt * 16 + (lane >> 2)) * FRW + (lane & 3) * 2) * 4);
    const unsigned fr1 = fr0 + (unsigned)(8 * FRW * 4);

    // owner identity: thread owns (j0 = tid>>3, j1 = j0+32, b = tid&7)
    const int j0 = tid >> 3;
    const int j1 = j0 + 32;
    const int b = tid & 7;
    const int bg = g * BG + b;
    const int jg0 = r * JS + j0;
    const int jg1 = r * JS + j1;
    const int len = lengths[bg];
    const float cp0 = g_cp[bg * HH + jg0];
    const float cp1 = g_cp[bg * HH + jg1];

    float* out0 = out + (size_t)bg * TT * HH + jg0;
    float* out1 = out + (size_t)bg * TT * HH + jg1;
    float* last0 = out + (size_t)BB * TT * HH + (size_t)bg * HH + jg0;
    float* last1 = out + (size_t)BB * TT * HH + (size_t)bg * HH + jg1;

    const unsigned fo0 = sb + FRAG_OFF + (unsigned)((j0 * FRW + b) * 4);
    const unsigned fo1 = sb + FRAG_OFF + (unsigned)((j1 * FRW + b) * 4);
    const unsigned fkh = (unsigned)(JS * FRW * 4);

    // staging identity: fixed k4s = (tid&127)*4; source rank = k4s>>6
    const int k4s = (tid & 127) * 4;
    const int srcrank = (tid & 127) >> 4;
    int* srcflag = &g_flag[g][srcrank * 8];
    int* myflag = &g_flag[g][r * 8];

    float xp0 = *out0;                 // prefetch xp for t=0
    float xp1 = *out1;

    __syncthreads();

    for (int t = 0; t < TT; t++) {
        const int w = (t & 1) ^ 1;

        // ---- dot via tensor cores (3 independent accumulators) ----
        float ca[4] = {0, 0, 0, 0}, cb[4] = {0, 0, 0, 0}, cc[4] = {0, 0, 0, 0};
#pragma unroll
        for (int ks = 0; ks < 16; ks++) {
            const unsigned ko = (unsigned)(ks * 32);
            uint32_t ah[4], al[4], bh0, bh1, bl0, bl1;
            ldsm_x4(aHi + ko, ah[0], ah[1], ah[2], ah[3]);
            ldsm_x4(aLo + ko, al[0], al[1], al[2], al[3]);
            ldsm_x2(bHi + ko, bh0, bh1);
            ldsm_x2(bLo + ko, bl0, bl1);
            mma16816(ca, ah, bh0, bh1);
            mma16816(cb, ah, bl0, bl1);
            mma16816(cc, al, bh0, bh1);
        }
        sts64f(fr0, ca[0] + cb[0] + cc[0], ca[1] + cb[1] + cc[1]);
        sts64f(fr1, ca[2] + cb[2] + cc[2], ca[3] + cb[3] + cc[3]);
        __syncthreads();

        // ---- owner: 2-way kh reduce, tanh, publish packed hi|lo ----
        float d0 = lds32v(fo0) + lds32v(fo0 + fkh);
        float d1 = lds32v(fo1) + lds32v(fo1 + fkh);

        const bool act = (t < len);
        float v0 = tanhf(d0 + xp0 + cp0);
        float v1 = tanhf(d1 + xp1 + cp1);

        __nv_bfloat16 vh0 = __float2bfloat16(v0);
        __nv_bfloat16 vl0 = __float2bfloat16(v0 - __bfloat162float(vh0));
        unsigned pk0 = ((unsigned)*(unsigned short*)&vl0 << 16) |
                       (unsigned)*(unsigned short*)&vh0;
        __nv_bfloat16 vh1 = __float2bfloat16(v1);
        __nv_bfloat16 vl1 = __float2bfloat16(v1 - __bfloat162float(vh1));
        unsigned pk1 = ((unsigned)*(unsigned short*)&vl1 << 16) |
                       (unsigned)*(unsigned short*)&vh1;
        __stcg(&g_hp[w][bg][jg0], pk0);
        __stcg(&g_hp[w][bg][jg1], pk1);

        out0[(size_t)t * HH] = act ? v0 : 0.0f;
        out1[(size_t)t * HH] = act ? v1 : 0.0f;
        if (t == len - 1) { *last0 = v0; *last1 = v1; }

        if (t == TT - 1) break;

        xp0 = out0[(size_t)(t + 1) * HH];  // prefetch under sync window
        xp1 = out1[(size_t)(t + 1) * HH];

        __syncthreads();
        if (tid == 0) {
            asm volatile("st.release.gpu.global.s32 [%0], %1;"
                         :: "l"(myflag), "r"(t + 1) : "memory");
        }

        // ---- poll only this thread's source rank, then stage its slice ----
        {
            int fv;
            do {
                asm volatile("ld.acquire.gpu.global.s32 %0, [%1];"
                             : "=r"(fv) : "l"(srcflag) : "memory");
            } while (fv < t + 1);
        }
#pragma unroll
        for (int i = 0; i < 4; i++) {
            int b_i = (tid >> 7) + i * 2;       // 2 batches per 256-thread pass
            uint4 q = __ldcg((const uint4*)&g_hp[w][g * BG + b_i][k4s]);
            uint32_t hi0 = prmt(q.x, q.y, 0x5410u);
            uint32_t hi1 = prmt(q.z, q.w, 0x5410u);
            uint32_t lo0 = prmt(q.x, q.y, 0x7632u);
            uint32_t lo1 = prmt(q.z, q.w, 0x7632u);
            unsigned dst = sb + HHI_OFF + (unsigned)((b_i * WSTR + k4s) * 2);
            sts64u(dst, hi0, hi1);
            sts64u(dst + (HLO_OFF - HHI_OFF), lo0, lo1);
        }
        __syncthreads();
    }
}

// ---------------- launch -------------------------------------------------------

extern "C" void kernel_launch(void* const* d_in, const int* in_sizes, int n_in,
                              void* d_out, int out_size)
{
    const float* x       = (const float*)d_in[0];
    const float* cons    = (const float*)d_in[1];
    const int*   lengths = (const int*)d_in[2];
    const float* W_ih    = (const float*)d_in[3];
    const float* b_ih    = (const float*)d_in[4];
    const float* W_hh    = (const float*)d_in[5];
    const float* b_hh    = (const float*)d_in[6];
    const float* W_ch    = (const float*)d_in[7];
    const float* b_ch    = (const float*)d_in[8];
    float* out = (float*)d_out;

    // Reset per-rank flags (captured memset node)
    void* flag_addr = nullptr;
    cudaGetSymbolAddress(&flag_addr, g_flag);
    cudaMemsetAsync(flag_addr, 0, sizeof(int) * NG * GR * 8);

    // Kernel order: cvt, xp, cp, scan (scan is the ncu-captured launch)
    cvt_kernel<<<4096, 256>>>(x, W_ih);

    // Phase A: xp = x @ W_ih^T + b_ih via mma.sync (bf16 split-precision)
    cudaFuncSetAttribute(xp_mma_kernel,
                         cudaFuncAttributeMaxDynamicSharedMemorySize, SMEM_X);
    xp_mma_kernel<<<dim3(8, (BB * TT) / 128), 256, SMEM_X>>>(b_ih, out);

    // Phase B: cp
    cp_kernel<<<BB, HH>>>(cons, W_ch, b_ch, b_hh);

    // Phase C: recurrence (128 CTAs, 1 per SM)
    cudaFuncSetAttribute(rnn_scan_kernel,
                         cudaFuncAttributeMaxDynamicSharedMemorySize, SMEM_C);
    rnn_scan_kernel<<<NG * GR, 256, SMEM_C>>>(out, W_hh, lengths);
}

// round 14
// speedup vs baseline: 1.5385x; 1.5385x over previous
#include <cuda_runtime.h>
#include <cuda_bf16.h>
#include <cstdint>

// Problem constants
#define BB   128
#define TT   1024
#define II   256
#define HH   512
#define CC   32

#define GR   8          // CTAs per group (W split 8 ways)
#define NG   16         // 16 groups (8 batches each)
#define BG   8          // batches per group
#define JS   64         // j rows per CTA

typedef unsigned long long ull;

// ---------------- generic asm helpers ----------------

__device__ __forceinline__ unsigned smem_u32(const void* p) {
    return (unsigned)__cvta_generic_to_shared(p);
}

__device__ __forceinline__ float lds32v(unsigned a) {
    float v;
    asm volatile("ld.shared.f32 %0, [%1];" : "=f"(v) : "r"(a));
    return v;
}

__device__ __forceinline__ void sts128v(unsigned a, uint4 v) {
    asm volatile("st.shared.v4.b32 [%0], {%1,%2,%3,%4};"
                 :: "r"(a), "r"(v.x), "r"(v.y), "r"(v.z), "r"(v.w) : "memory");
}

__device__ __forceinline__ void sts64u(unsigned a, uint32_t x, uint32_t y) {
    asm volatile("st.shared.v2.b32 [%0], {%1,%2};"
                 :: "r"(a), "r"(x), "r"(y) : "memory");
}

__device__ __forceinline__ void sts64f(unsigned a, float x, float y) {
    asm volatile("st.shared.v2.f32 [%0], {%1,%2};"
                 :: "r"(a), "f"(x), "f"(y) : "memory");
}

__device__ __forceinline__ void ldsm_x4(unsigned addr, uint32_t& r0, uint32_t& r1,
                                        uint32_t& r2, uint32_t& r3) {
    asm volatile("ldmatrix.sync.aligned.m8n8.x4.shared.b16 {%0,%1,%2,%3}, [%4];"
                 : "=r"(r0), "=r"(r1), "=r"(r2), "=r"(r3) : "r"(addr));
}

__device__ __forceinline__ void ldsm_x2(unsigned addr, uint32_t& r0, uint32_t& r1) {
    asm volatile("ldmatrix.sync.aligned.m8n8.x2.shared.b16 {%0,%1}, [%2];"
                 : "=r"(r0), "=r"(r1) : "r"(addr));
}

__device__ __forceinline__ void mma16816(float* c, const uint32_t* a,
                                         uint32_t b0, uint32_t b1) {
    asm volatile(
        "mma.sync.aligned.m16n8k16.row.col.f32.bf16.bf16.f32 "
        "{%0,%1,%2,%3}, {%4,%5,%6,%7}, {%8,%9}, {%0,%1,%2,%3};"
        : "+f"(c[0]), "+f"(c[1]), "+f"(c[2]), "+f"(c[3])
        : "r"(a[0]), "r"(a[1]), "r"(a[2]), "r"(a[3]), "r"(b0), "r"(b1));
}

// split a float4 into bf16x2 hi/lo register pairs
__device__ __forceinline__ void split4(float4 v, uint2& hv, uint2& lv) {
    __nv_bfloat162 h01 = __floats2bfloat162_rn(v.x, v.y);
    __nv_bfloat162 h23 = __floats2bfloat162_rn(v.z, v.w);
    float l0 = v.x - __bfloat162float(h01.x);
    float l1 = v.y - __bfloat162float(h01.y);
    float l2 = v.z - __bfloat162float(h23.x);
    float l3 = v.w - __bfloat162float(h23.y);
    __nv_bfloat162 q01 = __floats2bfloat162_rn(l0, l1);
    __nv_bfloat162 q23 = __floats2bfloat162_rn(l2, l3);
    hv = make_uint2(*(uint32_t*)&h01, *(uint32_t*)&h23);
    lv = make_uint2(*(uint32_t*)&q01, *(uint32_t*)&q23);
}

// ---------------- Pre-pass: split x and W_ih into bf16 hi/lo ----------------

#define NX4 ((BB * TT * II) / 4)   // 8388608 float4 groups
#define NW4 ((HH * II) / 4)        // 32768

__device__ __nv_bfloat16 g_xhi[BB * TT * II];
__device__ __nv_bfloat16 g_xlo[BB * TT * II];
__device__ __nv_bfloat16 g_whi[HH * II];
__device__ __nv_bfloat16 g_wlo[HH * II];

__global__ void __launch_bounds__(256)
cvt_kernel(const float* __restrict__ x, const float* __restrict__ w)
{
    const int stride = gridDim.x * blockDim.x;
    for (int i = blockIdx.x * blockDim.x + threadIdx.x; i < NX4 + NW4; i += stride) {
        float4 v = (i < NX4) ? ((const float4*)x)[i]
                             : ((const float4*)w)[i - NX4];
        uint2 hv, lv;
        split4(v, hv, lv);
        if (i < NX4) {
            ((uint2*)g_xhi)[i] = hv;
            ((uint2*)g_xlo)[i] = lv;
        } else {
            ((uint2*)g_whi)[i - NX4] = hv;
            ((uint2*)g_wlo)[i - NX4] = lv;
        }
    }
}

// ---------------- Kernel A: xp via mma.sync bf16 split-precision (R10) ---------

#define KC     64
#define ASTR   72                     // bf16 stride
#define XA_HI  0
#define XA_LO  (128 * ASTR * 2)       // 18432
#define XB_HI  (2 * 128 * ASTR * 2)   // 36864
#define XB_LO  (XB_HI + 64 * ASTR * 2)
#define SMEM_X (XB_LO + 64 * ASTR * 2)  // 55296 bytes

__global__ void __launch_bounds__(256)
xp_mma_kernel(const float* __restrict__ bias, float* __restrict__ out)
{
    extern __shared__ char smx[];
    const unsigned sb = smem_u32(smx);
    const int tid = threadIdx.x;
    const int wid = tid >> 5;
    const int lane = tid & 31;
    const int h0 = blockIdx.x * 64;
    const int m0 = blockIdx.y * 128;

    const int wr = wid >> 1;
    const int wc = wid & 1;

    float acc[2][4][4];
#pragma unroll
    for (int mt = 0; mt < 2; mt++)
#pragma unroll
        for (int nt = 0; nt < 4; nt++)
#pragma unroll
            for (int i = 0; i < 4; i++) acc[mt][nt][i] = 0.0f;

    const int a_row = wr * 32 + (lane & 15);
    const int a_col = (lane >> 4) * 8;
    const unsigned a_addr0 = sb + XA_HI + (unsigned)((a_row * ASTR + a_col) * 2);
    const int b_n = wc * 32 + (lane & 7) + (lane >> 4) * 8;
    const int b_k = ((lane >> 3) & 1) * 8;
    const unsigned b_addr0 = sb + XB_HI + (unsigned)((b_n * ASTR + b_k) * 2);

    for (int ch = 0; ch < 4; ch++) {
        __syncthreads();
        {
#pragma unroll
            for (int i = 0; i < 4; i++) {
                int idx = tid + i * 256;
                int row = idx >> 3;
                int c8 = idx & 7;
                size_t src = (size_t)(m0 + row) * II + ch * KC + c8 * 8;
                unsigned dst = (unsigned)((row * ASTR + c8 * 8) * 2);
                sts128v(sb + XA_HI + dst, *(const uint4*)(g_xhi + src));
                sts128v(sb + XA_LO + dst, *(const uint4*)(g_xlo + src));
            }
        }
        {
#pragma unroll
            for (int i = 0; i < 2; i++) {
                int idx = tid + i * 256;
                int row = idx >> 3;
                int c8 = idx & 7;
                size_t src = (size_t)(h0 + row) * II + ch * KC + c8 * 8;
                unsigned dst = (unsigned)((row * ASTR + c8 * 8) * 2);
                sts128v(sb + XB_HI + dst, *(const uint4*)(g_whi + src));
                sts128v(sb + XB_LO + dst, *(const uint4*)(g_wlo + src));
            }
        }
        __syncthreads();

#pragma unroll
        for (int kk = 0; kk < 4; kk++) {
            const unsigned akk = (unsigned)(kk * 16 * 2);
            uint32_t ah[2][4], al[2][4];
#pragma unroll
            for (int mt = 0; mt < 2; mt++) {
                unsigned ao = a_addr0 + akk + (unsigned)(mt * 16 * ASTR * 2);
                ldsm_x4(ao, ah[mt][0], ah[mt][1], ah[mt][2], ah[mt][3]);
                ldsm_x4(ao + (XA_LO - XA_HI),
                        al[mt][0], al[mt][1], al[mt][2], al[mt][3]);
            }
            uint32_t bh[2][4], bl[2][4];
#pragma unroll
            for (int np = 0; np < 2; np++) {
                unsigned bo = b_addr0 + akk + (unsigned)(np * 16 * ASTR * 2);
                ldsm_x4(bo, bh[np][0], bh[np][1], bh[np][2], bh[np][3]);
                ldsm_x4(bo + (XB_LO - XB_HI),
                        bl[np][0], bl[np][1], bl[np][2], bl[np][3]);
            }
#pragma unroll
            for (int mt = 0; mt < 2; mt++)
#pragma unroll
                for (int np = 0; np < 2; np++)
#pragma unroll
                    for (int sub = 0; sub < 2; sub++) {
                        float* c = acc[mt][np * 2 + sub];
                        mma16816(c, ah[mt], bh[np][sub * 2], bh[np][sub * 2 + 1]);
                        mma16816(c, ah[mt], bl[np][sub * 2], bl[np][sub * 2 + 1]);
                        mma16816(c, al[mt], bh[np][sub * 2], bh[np][sub * 2 + 1]);
                    }
        }
    }

    const int g = lane >> 2;
    const int tig = lane & 3;
#pragma unroll
    for (int mt = 0; mt < 2; mt++) {
        const int row0 = m0 + wr * 32 + mt * 16 + g;
#pragma unroll
        for (int nt = 0; nt < 4; nt++) {
            const int col = h0 + wc * 32 + nt * 8 + tig * 2;
            float2 bv = *(const float2*)&bias[col];
            float* c = acc[mt][nt];
            float2 o0 = make_float2(c[0] + bv.x, c[1] + bv.y);
            float2 o1 = make_float2(c[2] + bv.x, c[3] + bv.y);
            *(float2*)&out[(size_t)row0 * HH + col] = o0;
            *(float2*)&out[(size_t)(row0 + 8) * HH + col] = o1;
        }
    }
}

// ---------------- Kernel B ------------------------------------------------------

__device__ float g_cp[BB * HH];
__device__ float g_h[2][BB][HH];         // h exchange (L2)
__device__ int   g_cnt[2][NG][32];       // group arrival counters

__global__ void __launch_bounds__(512)
cp_kernel(const float* __restrict__ cons, const float* __restrict__ W_ch,
          const float* __restrict__ b_ch, const float* __restrict__ b_hh)
{
    __shared__ float cs[CC];
    const int b = blockIdx.x;
    const int h = threadIdx.x;
    if (h < CC) cs[h] = cons[b * CC + h];
    __syncthreads();
    float s = b_ch[h] + b_hh[h];
#pragma unroll
    for (int c = 0; c < CC; c++) s += cs[c] * W_ch[h * CC + c];
    g_cp[b * HH + h] = s;
}

// ---------------- Kernel C: recurrence via tensor cores (R11 + W-in-registers) --
// Per CTA (group g, rank r): D[64j,8b] = Wslice[64,512] @ h^T via bf16 split
// mma.sync. 8 warps = 4 m-tiles x 2 k-halves. W fragments preloaded into
// registers ONCE (invariant over t) — per-step dot is only h ldsm + MMA.
// Sync: R11's proven counter protocol (single poller per CTA).

#define WSTR    520                   // bf16 row stride
#define WHI_OFF 0
#define WLO_OFF (JS * WSTR * 2)                 // 66560
#define HHI_OFF (2 * JS * WSTR * 2)             // 133120
#define HLO_OFF (HHI_OFF + BG * WSTR * 2)       // 141440
#define FRAG_OFF (HLO_OFF + BG * WSTR * 2)      // 149760
#define FRW     10                    // frag row stride (floats)
#define SMEM_C  (FRAG_OFF + 2 * JS * FRW * 4 + 128)  // ~155 KB

__global__ void __launch_bounds__(256, 1)
rnn_scan_kernel(float* __restrict__ out, const float* __restrict__ W_hh,
                const int* __restrict__ lengths)
{
    extern __shared__ char smc[];
    const unsigned sb = smem_u32(smc);
    const int tid = threadIdx.x;
    const int r = blockIdx.x & 7;
    const int g = blockIdx.x >> 3;

    // one-time: convert W slice to bf16 hi/lo in SMEM
    for (int idx = tid; idx < (JS * HH) / 4; idx += 256) {
        int j = idx >> 7;
        int k4 = (idx & 127) * 4;
        float4 v = *(const float4*)&W_hh[(size_t)(r * JS + j) * HH + k4];
        uint2 hv, lv;
        split4(v, hv, lv);
        unsigned dst = sb + WHI_OFF + (unsigned)((j * WSTR + k4) * 2);
        sts64u(dst, hv.x, hv.y);
        sts64u(dst + (WLO_OFF - WHI_OFF), lv.x, lv.y);
    }
    // zero h hi/lo (h at t=0 is 0)
    for (int idx = tid; idx < (2 * BG * WSTR * 2) / 4; idx += 256) {
        asm volatile("st.shared.b32 [%0], %1;"
                     :: "r"(sb + HHI_OFF + (unsigned)(idx * 4)), "r"(0u) : "memory");
    }

    const int wid = tid >> 5;
    const int lane = tid & 31;
    const int mt = wid >> 1;            // m-tile (0..3)
    const int kh = wid & 1;             // k-half (0..1)

    // ldsm addresses (validated maps)
    const unsigned aHi = sb + WHI_OFF +
        (unsigned)(((mt * 16 + (lane & 15)) * WSTR + kh * 256 + (lane >> 4) * 8) * 2);
    const unsigned aLo = aHi + (WLO_OFF - WHI_OFF);
    const int l4 = lane & 15;
    const unsigned bHi = sb + HHI_OFF +
        (unsigned)(((l4 & 7) * WSTR + kh * 256 + ((l4 >> 3) & 1) * 8) * 2);
    const unsigned bLo = bHi + (HLO_OFF - HHI_OFF);

    // frag store addrs
    const unsigned fr0 = sb + FRAG_OFF +
        (unsigned)(((kh * JS + mt * 16 + (lane >> 2)) * FRW + (lane & 3) * 2) * 4);
    const unsigned fr1 = fr0 + (unsigned)(8 * FRW * 4);

    // owner identity: thread owns (j0 = tid>>3, j1 = j0+32, b = tid&7)
    const int j0 = tid >> 3;
    const int j1 = j0 + 32;
    const int b = tid & 7;
    const int bg = g * BG + b;
    const int jg0 = r * JS + j0;
    const int jg1 = r * JS + j1;
    const int len = lengths[bg];
    const float cp0 = g_cp[bg * HH + jg0];
    const float cp1 = g_cp[bg * HH + jg1];

    float* out0 = out + (size_t)bg * TT * HH + jg0;
    float* out1 = out + (size_t)bg * TT * HH + jg1;
    float* last0 = out + (size_t)BB * TT * HH + (size_t)bg * HH + jg0;
    float* last1 = out + (size_t)BB * TT * HH + (size_t)bg * HH + jg1;

    const unsigned fo0 = sb + FRAG_OFF + (unsigned)((j0 * FRW + b) * 4);
    const unsigned fo1 = sb + FRAG_OFF + (unsigned)((j1 * FRW + b) * 4);
    const unsigned fkh = (unsigned)(JS * FRW * 4);

    int* cnt1 = &g_cnt[1][g][0];
    int* cnt0 = &g_cnt[0][g][0];

    float xp0 = *out0;                 // prefetch xp for t=0
    float xp1 = *out1;

    __syncthreads();

    // ---- preload W fragments into registers (invariant over t) ----
    uint32_t wah[16][4], wal[16][4];
#pragma unroll
    for (int ks = 0; ks < 16; ks++) {
        const unsigned ko = (unsigned)(ks * 32);
        ldsm_x4(aHi + ko, wah[ks][0], wah[ks][1], wah[ks][2], wah[ks][3]);
        ldsm_x4(aLo + ko, wal[ks][0], wal[ks][1], wal[ks][2], wal[ks][3]);
    }

    for (int t = 0; t < TT; t++) {
        const int w = (t & 1) ^ 1;

        // ---- dot via tensor cores (W resident; only h loaded per step) ----
        float ca[4] = {0, 0, 0, 0}, cb[4] = {0, 0, 0, 0}, cc[4] = {0, 0, 0, 0};
#pragma unroll
        for (int ks = 0; ks < 16; ks++) {
            const unsigned ko = (unsigned)(ks * 32);
            uint32_t bh0, bh1, bl0, bl1;
            ldsm_x2(bHi + ko, bh0, bh1);
            ldsm_x2(bLo + ko, bl0, bl1);
            mma16816(ca, wah[ks], bh0, bh1);
            mma16816(cb, wah[ks], bl0, bl1);
            mma16816(cc, wal[ks], bh0, bh1);
        }
        sts64f(fr0, ca[0] + cb[0] + cc[0], ca[1] + cb[1] + cc[1]);
        sts64f(fr1, ca[2] + cb[2] + cc[2], ca[3] + cb[3] + cc[3]);
        __syncthreads();

        // ---- owner: 2-way kh reduce, tanh, publish ----
        float d0 = lds32v(fo0) + lds32v(fo0 + fkh);
        float d1 = lds32v(fo1) + lds32v(fo1 + fkh);

        const bool act = (t < len);
        float v0 = tanhf(d0 + xp0 + cp0);
        float v1 = tanhf(d1 + xp1 + cp1);

        __stcg(&g_h[w][bg][jg0], v0);
        __stcg(&g_h[w][bg][jg1], v1);

        out0[(size_t)t * HH] = act ? v0 : 0.0f;
        out1[(size_t)t * HH] = act ? v1 : 0.0f;
        if (t == len - 1) { *last0 = v0; *last1 = v1; }

        if (t == TT - 1) break;

        xp0 = out0[(size_t)(t + 1) * HH];  // prefetch under sync window
        xp1 = out1[(size_t)(t + 1) * HH];

        __syncthreads();
        if (tid == 0) {
            int* cw = w ? cnt1 : cnt0;
            asm volatile("red.release.gpu.global.add.s32 [%0], %1;"
                         :: "l"(cw), "r"(1) : "memory");
            const int target = ((t >> 1) + 1) * GR;
            int v;
            do {
                asm volatile("ld.acquire.gpu.global.s32 %0, [%1];"
                             : "=r"(v) : "l"(cw) : "memory");
            } while (v < target);
        }
        __syncthreads();

        // ---- stage: read full h (L2), split to bf16 hi/lo in SMEM ----
        {
#pragma unroll
            for (int i = 0; i < 4; i++) {
                int idx = tid + i * 256;       // 0..1023 float4 granules
                int b_i = idx >> 7;            // 0..7
                int k4 = (idx & 127) * 4;      // 0..508
                float4 v4 = __ldcg((const float4*)&g_h[w][g * BG + b_i][k4]);
                uint2 hv, lv;
                split4(v4, hv, lv);
                unsigned dst = sb + HHI_OFF + (unsigned)((b_i * WSTR + k4) * 2);
                sts64u(dst, hv.x, hv.y);
                sts64u(dst + (HLO_OFF - HHI_OFF), lv.x, lv.y);
            }
        }
        __syncthreads();
    }
}

// ---------------- launch -------------------------------------------------------

extern "C" void kernel_launch(void* const* d_in, const int* in_sizes, int n_in,
                              void* d_out, int out_size)
{
    const float* x       = (const float*)d_in[0];
    const float* cons    = (const float*)d_in[1];
    const int*   lengths = (const int*)d_in[2];
    const float* W_ih    = (const float*)d_in[3];
    const float* b_ih    = (const float*)d_in[4];
    const float* W_hh    = (const float*)d_in[5];
    const float* b_hh    = (const float*)d_in[6];
    const float* W_ch    = (const float*)d_in[7];
    const float* b_ch    = (const float*)d_in[8];
    float* out = (float*)d_out;

    // Reset group counters
    void* cnt_addr = nullptr;
    cudaGetSymbolAddress(&cnt_addr, g_cnt);
    cudaMemsetAsync(cnt_addr, 0, sizeof(int) * 2 * NG * 32);

    // Kernel order: cvt, xp, cp, scan (scan is the ncu-captured launch)
    cvt_kernel<<<4096, 256>>>(x, W_ih);

    // Phase A: xp = x @ W_ih^T + b_ih via mma.sync (bf16 split-precision)
    cudaFuncSetAttribute(xp_mma_kernel,
                         cudaFuncAttributeMaxDynamicSharedMemorySize, SMEM_X);
    xp_mma_kernel<<<dim3(8, (BB * TT) / 128), 256, SMEM_X>>>(b_ih, out);

    // Phase B: cp
    cp_kernel<<<BB, HH>>>(cons, W_ch, b_ch, b_hh);

    // Phase C: recurrence (128 CTAs, 1 per SM)
    cudaFuncSetAttribute(rnn_scan_kernel,
                         cudaFuncAttributeMaxDynamicSharedMemorySize, SMEM_C);
    rnn_scan_kernel<<<NG * GR, 256, SMEM_C>>>(out, W_hh, lengths);
}